// round 1
// baseline (speedup 1.0000x reference)
#include <cuda_runtime.h>
#include <math.h>
#include <stdint.h>

// Problem shapes (fixed for this bench)
#define BB 4
#define TT 512
#define SS 1024
#define HH 768
#define VV 50257

// Padded accumulator length (multiple of 4 for vectorized zeroing) + 32-float
// reduction scratch at the tail.
#define VPAD 50260
#define SMEM_FLOATS (VPAD + 32)
#define SMEM_BYTES (SMEM_FLOATS * 4)

// Scratch for the collapsed p_gen projections (device globals: no allocation).
__device__ float g_u[BB * SS];   // u[b,s] = src[b,s,:] . W_pgen[:H]
__device__ float g_v[BB * TT];   // v[b,t] = tgt[b,t,:] . W_pgen[H:] + bias

// ---------------------------------------------------------------------------
// Kernel 1: tiny projections. One warp per row (B*S + B*T = 6144 rows).
// ---------------------------------------------------------------------------
__global__ void pgen_prep_kernel(const float* __restrict__ src,
                                 const float* __restrict__ tgt,
                                 const float* __restrict__ W,
                                 const float* __restrict__ bias)
{
    const int warp = (blockIdx.x * blockDim.x + threadIdx.x) >> 5;
    const int lane = threadIdx.x & 31;
    const int NU = BB * SS;
    const int NV = BB * TT;

    if (warp < NU) {
        // u[b,s]
        const float4* x = reinterpret_cast<const float4*>(src + (size_t)warp * HH);
        const float4* w = reinterpret_cast<const float4*>(W);
        float acc = 0.f;
        #pragma unroll
        for (int j = lane; j < HH / 4; j += 32) {
            float4 a = x[j], b = w[j];
            acc += a.x * b.x + a.y * b.y + a.z * b.z + a.w * b.w;
        }
        #pragma unroll
        for (int o = 16; o; o >>= 1) acc += __shfl_xor_sync(0xffffffffu, acc, o);
        if (lane == 0) g_u[warp] = acc;
    } else if (warp < NU + NV) {
        // v[b,t]
        const int r = warp - NU;
        const float4* x = reinterpret_cast<const float4*>(tgt + (size_t)r * HH);
        const float4* w = reinterpret_cast<const float4*>(W + HH);
        float acc = 0.f;
        #pragma unroll
        for (int j = lane; j < HH / 4; j += 32) {
            float4 a = x[j], b = w[j];
            acc += a.x * b.x + a.y * b.y + a.z * b.z + a.w * b.w;
        }
        #pragma unroll
        for (int o = 16; o; o >>= 1) acc += __shfl_xor_sync(0xffffffffu, acc, o);
        if (lane == 0) g_v[r] = acc + bias[0];
    }
}

// ---------------------------------------------------------------------------
// Kernel 2: one CTA per (b,t) row. Shared-memory vocab accumulator:
//   zero -> shared-atomic scatter of attn weights -> stream row to GMEM.
// Fuses the p_gen reduction (attn . u) using the attn values already loaded.
// ---------------------------------------------------------------------------
__global__ __launch_bounds__(1024, 1)
void copy_logits_kernel(const int* __restrict__ ids,
                        const float* __restrict__ attn,
                        float* __restrict__ out_pgen,
                        float* __restrict__ out_logits)
{
    extern __shared__ float sm[];          // [VPAD] accumulator + [32] reduce
    const int row = blockIdx.x;            // b*T + t
    const int b   = row / TT;
    const int tid = threadIdx.x;

    // Phase 1: zero the accumulator (vectorized).
    float4* sm4 = reinterpret_cast<float4*>(sm);
    const float4 z4 = make_float4(0.f, 0.f, 0.f, 0.f);
    #pragma unroll 4
    for (int i = tid; i < VPAD / 4; i += 1024) sm4[i] = z4;
    __syncthreads();

    // Phase 2: scatter-add + p_gen partial. Exactly S=1024 threads, 1 each.
    const float a = attn[(size_t)row * SS + tid];
    const int   id = ids[b * SS + tid];
    atomicAdd(&sm[id], a);

    float part = a * g_u[b * SS + tid];
    #pragma unroll
    for (int o = 16; o; o >>= 1) part += __shfl_xor_sync(0xffffffffu, part, o);
    float* red = sm + VPAD;
    if ((tid & 31) == 0) red[tid >> 5] = part;
    __syncthreads();   // atomics + warp partials complete

    if (tid < 32) {
        float x = red[tid];
        #pragma unroll
        for (int o = 16; o; o >>= 1) x += __shfl_xor_sync(0xffffffffu, x, o);
        if (tid == 0) {
            const float zv = x + g_v[row];
            out_pgen[row] = 1.f / (1.f + __expf(-zv));
        }
    }

    // Phase 3: stream the full row out (no re-read; evict-first stores).
    float* dst = out_logits + (size_t)row * VV;
    for (int v = tid; v < VV; v += 1024) __stcs(dst + v, sm[v]);
}

// ---------------------------------------------------------------------------
// Launch
// ---------------------------------------------------------------------------
extern "C" void kernel_launch(void* const* d_in, const int* in_sizes, int n_in,
                              void* d_out, int out_size)
{
    const int*   ids  = (const int*)  d_in[0];  // [B,S] int32
    const float* attn = (const float*)d_in[1];  // [B,T,S]
    const float* src  = (const float*)d_in[2];  // [B,S,H]
    const float* tgt  = (const float*)d_in[3];  // [B,T,H]
    const float* W    = (const float*)d_in[4];  // [2H,1]
    const float* bias = (const float*)d_in[5];  // [1]

    float* out_pgen   = (float*)d_out;              // [B,T]  (first output)
    float* out_logits = out_pgen + (size_t)BB * TT; // [B,T,V]

    cudaFuncSetAttribute(copy_logits_kernel,
                         cudaFuncAttributeMaxDynamicSharedMemorySize,
                         SMEM_BYTES);

    // 6144 warp-rows -> 768 blocks x 256 threads
    pgen_prep_kernel<<<(BB * SS + BB * TT) / 8, 256>>>(src, tgt, W, bias);

    copy_logits_kernel<<<BB * TT, 1024, SMEM_BYTES>>>(ids, attn, out_pgen,
                                                      out_logits);
}

// round 2
// speedup vs baseline: 1.0206x; 1.0206x over previous
#include <cuda_runtime.h>
#include <math.h>
#include <stdint.h>

// Problem shapes (fixed for this bench)
#define BB 4
#define TT 512
#define SS 1024
#define HH 768
#define VV 50257

// Vocab split: two CTAs per (b,t) row.
#define VLO1   25129                 // half0 = [0,25129), half1 = [25129,50257)
#define VHALF_MAX 25129
#define VPADH  25132                 // padded to multiple of 4
#define SMEM_FLOATS (VPADH + 32)
#define SMEM_BYTES  (SMEM_FLOATS * 4)

// Scratch for the collapsed p_gen projections (device globals: no allocation).
__device__ float g_u[BB * SS];   // u[b,s] = src[b,s,:] . W_pgen[:H]
__device__ float g_v[BB * TT];   // v[b,t] = tgt[b,t,:] . W_pgen[H:] + bias

// ---------------------------------------------------------------------------
// Kernel 1: tiny projections. One warp per row (B*S + B*T = 6144 rows).
// ---------------------------------------------------------------------------
__global__ void pgen_prep_kernel(const float* __restrict__ src,
                                 const float* __restrict__ tgt,
                                 const float* __restrict__ W,
                                 const float* __restrict__ bias)
{
    const int warp = (blockIdx.x * blockDim.x + threadIdx.x) >> 5;
    const int lane = threadIdx.x & 31;
    const int NU = BB * SS;
    const int NV = BB * TT;

    if (warp < NU) {
        const float4* x = reinterpret_cast<const float4*>(src + (size_t)warp * HH);
        const float4* w = reinterpret_cast<const float4*>(W);
        float acc = 0.f;
        #pragma unroll
        for (int j = lane; j < HH / 4; j += 32) {
            float4 a = x[j], b = w[j];
            acc += a.x * b.x + a.y * b.y + a.z * b.z + a.w * b.w;
        }
        #pragma unroll
        for (int o = 16; o; o >>= 1) acc += __shfl_xor_sync(0xffffffffu, acc, o);
        if (lane == 0) g_u[warp] = acc;
    } else if (warp < NU + NV) {
        const int r = warp - NU;
        const float4* x = reinterpret_cast<const float4*>(tgt + (size_t)r * HH);
        const float4* w = reinterpret_cast<const float4*>(W + HH);
        float acc = 0.f;
        #pragma unroll
        for (int j = lane; j < HH / 4; j += 32) {
            float4 a = x[j], b = w[j];
            acc += a.x * b.x + a.y * b.y + a.z * b.z + a.w * b.w;
        }
        #pragma unroll
        for (int o = 16; o; o >>= 1) acc += __shfl_xor_sync(0xffffffffu, acc, o);
        if (lane == 0) g_v[r] = acc + bias[0];
    }
}

// ---------------------------------------------------------------------------
// Kernel 2: two CTAs per (b,t) row, each owning half the vocab.
//   zero half-accumulator -> range-predicated shared-atomic scatter
//   -> vectorized streaming store of the half-row.
// ~100KB smem per CTA -> 2 CTAs/SM: one CTA's zero/scatter overlaps the
// other's DRAM-bound streaming. p_gen fused into the half-0 CTA.
// ---------------------------------------------------------------------------
__global__ __launch_bounds__(1024, 2)
void copy_logits_kernel(const int* __restrict__ ids,
                        const float* __restrict__ attn,
                        float* __restrict__ out_pgen,
                        float* __restrict__ out_logits)
{
    extern __shared__ float sm[];          // [VPADH] accumulator + [32] reduce
    const int row  = blockIdx.x >> 1;      // b*T + t
    const int half = blockIdx.x & 1;
    const int b    = row / TT;
    const int tid  = threadIdx.x;

    const int lo = half ? VLO1 : 0;
    const int hi = half ? VV   : VLO1;
    const int n  = hi - lo;

    // Phase 1: zero the half-accumulator (vectorized STS.128).
    float4* sm4 = reinterpret_cast<float4*>(sm);
    const float4 z4 = make_float4(0.f, 0.f, 0.f, 0.f);
    #pragma unroll
    for (int i = tid; i < VPADH / 4; i += 1024) sm4[i] = z4;
    __syncthreads();

    // Phase 2: range-predicated scatter-add. Exactly S=1024 threads, 1 each.
    const float a  = attn[(size_t)row * SS + tid];
    const int   id = ids[b * SS + tid];
    if (id >= lo && id < hi) atomicAdd(&sm[id - lo], a);

    if (half == 0) {
        // Fused p_gen = sigmoid(attn . u + v) using the attn value in hand.
        float part = a * g_u[b * SS + tid];
        #pragma unroll
        for (int o = 16; o; o >>= 1) part += __shfl_xor_sync(0xffffffffu, part, o);
        float* red = sm + VPADH;
        if ((tid & 31) == 0) red[tid >> 5] = part;
        __syncthreads();   // atomics + warp partials complete
        if (tid < 32) {
            float x = red[tid];
            #pragma unroll
            for (int o = 16; o; o >>= 1) x += __shfl_xor_sync(0xffffffffu, x, o);
            if (tid == 0) {
                const float zv = x + g_v[row];
                out_pgen[row] = 1.f / (1.f + __expf(-zv));
            }
        }
    } else {
        __syncthreads();   // atomics complete
    }

    // Phase 3: stream the half-row out with STG.128 (evict-first), handling
    // the row's 16B misalignment (row stride 50257*4 ≡ 4 mod 16).
    float* dst = out_logits + (size_t)row * VV + lo;
    const int head = (int)(((16u - ((uint32_t)(uintptr_t)dst & 15u)) & 15u) >> 2);

    if (tid < head) __stcs(dst + tid, sm[tid]);

    const int nvec = (n - head) >> 2;
    float4* dst4 = reinterpret_cast<float4*>(dst + head);
    for (int i = tid; i < nvec; i += 1024) {
        const int j = head + 4 * i;
        float4 val;
        val.x = sm[j];
        val.y = sm[j + 1];
        val.z = sm[j + 2];
        val.w = sm[j + 3];
        __stcs(dst4 + i, val);
    }

    const int tail = head + 4 * nvec;
    if (tid < n - tail) __stcs(dst + tail + tid, sm[tail + tid]);
}

// ---------------------------------------------------------------------------
// Launch
// ---------------------------------------------------------------------------
extern "C" void kernel_launch(void* const* d_in, const int* in_sizes, int n_in,
                              void* d_out, int out_size)
{
    const int*   ids  = (const int*)  d_in[0];  // [B,S] int32
    const float* attn = (const float*)d_in[1];  // [B,T,S]
    const float* src  = (const float*)d_in[2];  // [B,S,H]
    const float* tgt  = (const float*)d_in[3];  // [B,T,H]
    const float* W    = (const float*)d_in[4];  // [2H,1]
    const float* bias = (const float*)d_in[5];  // [1]

    float* out_pgen   = (float*)d_out;              // [B,T]  (first output)
    float* out_logits = out_pgen + (size_t)BB * TT; // [B,T,V]

    cudaFuncSetAttribute(copy_logits_kernel,
                         cudaFuncAttributeMaxDynamicSharedMemorySize,
                         SMEM_BYTES);

    pgen_prep_kernel<<<(BB * SS + BB * TT) / 8, 256>>>(src, tgt, W, bias);

    copy_logits_kernel<<<BB * TT * 2, 1024, SMEM_BYTES>>>(ids, attn, out_pgen,
                                                          out_logits);
}